// round 2
// baseline (speedup 1.0000x reference)
#include <cuda_runtime.h>
#include <cstdint>

#define N_NODES 100000
#define N_EDGES 800000
#define C 128
#define EPS_BN 1e-5f

// ---------------- device scratch (no allocs allowed) ----------------
__device__ float g_agg[N_NODES * C];        // 51.2 MB
__device__ float g_deg[N_NODES];
__device__ float g_h1[N_NODES * C];         // 51.2 MB
__device__ float g_h2[N_NODES * C];         // 51.2 MB
__device__ float g_Wc[3][2 * C * C];        // packed [K=256][128] per layer
__device__ float g_Wh1p[C * C];             // padded head-1 weights [K=128][128]
__device__ float g_bh1p[C];
__device__ float g_sum[C];
__device__ float g_sumsq[C];
__device__ float g_scale[C];
__device__ float g_shift[C];
__device__ int g_src[N_EDGES];
__device__ int g_dst[N_EDGES];
__device__ int g_is64;

// ---------------- edge dtype detection + decode ----------------
// If edge_index is int64, the high 32-bit word of every element is 0
// (indices are in [0, 100000)). If int32, odd words are random nonzero values.
__global__ void detect_kernel(const int* __restrict__ w) {
    __shared__ int acc[256];
    int tid = threadIdx.x;
    int v = 0;
    // inspect odd words among the first 2048 words (buffer has >= 1.6M words)
    for (int i = tid; i < 1024; i += 256) v |= w[2 * i + 1];
    acc[tid] = v;
    __syncthreads();
    for (int s = 128; s > 0; s >>= 1) {
        if (tid < s) acc[tid] |= acc[tid + s];
        __syncthreads();
    }
    if (tid == 0) g_is64 = (acc[0] == 0) ? 1 : 0;
}

__global__ void decode_kernel(const int* __restrict__ w) {
    int e = blockIdx.x * blockDim.x + threadIdx.x;
    if (e >= N_EDGES) return;
    if (g_is64) {
        g_src[e] = w[2 * e];                 // low word of ei[0][e]
        g_dst[e] = w[2 * (N_EDGES + e)];     // low word of ei[1][e]
    } else {
        g_src[e] = w[e];
        g_dst[e] = w[N_EDGES + e];
    }
}

// ---------------- prep: pack weights transposed for coalesced B loads ----------------
__global__ void pack_pair_kernel(const float* __restrict__ Wn,
                                 const float* __restrict__ Wr,
                                 int layer) {
    int idx = blockIdx.x * blockDim.x + threadIdx.x;
    if (idx >= 2 * C * C) return;
    int k = idx / C, j = idx % C;
    g_Wc[layer][idx] = (k < C) ? Wn[j * C + k] : Wr[j * C + (k - C)];
}

__global__ void pack_head_kernel(const float* __restrict__ Wh1,
                                 const float* __restrict__ bh1) {
    int idx = blockIdx.x * blockDim.x + threadIdx.x;
    if (idx < C * C) {
        int k = idx / C, j = idx % C;
        g_Wh1p[idx] = (j < 64) ? Wh1[j * C + k] : 0.0f;
    }
    if (idx < C) g_bh1p[idx] = (idx < 64) ? bh1[idx] : 0.0f;
}

// ---------------- zero agg/deg/stats ----------------
__global__ void zero_kernel() {
    int stride = gridDim.x * blockDim.x;
    float4 z = make_float4(0.f, 0.f, 0.f, 0.f);
    for (int i = blockIdx.x * blockDim.x + threadIdx.x; i < N_NODES * C / 4; i += stride) {
        reinterpret_cast<float4*>(g_agg)[i] = z;
        if (i < N_NODES / 4) reinterpret_cast<float4*>(g_deg)[i] = z;
        if (i < C) { g_sum[i] = 0.f; g_sumsq[i] = 0.f; }
    }
}

// ---------------- edge scatter: warp per edge, vectorized L2 reduction ----------------
__global__ void scatter_kernel(const float* __restrict__ h) {
    int gtid = blockIdx.x * blockDim.x + threadIdx.x;
    int e = gtid >> 5;
    int lane = gtid & 31;
    if (e >= N_EDGES) return;
    int s = g_src[e];
    int d = g_dst[e];
    float4 v = *reinterpret_cast<const float4*>(h + (size_t)s * C + lane * 4);
    float* dstp = g_agg + (size_t)d * C + lane * 4;
    asm volatile("red.global.add.v4.f32 [%0], {%1,%2,%3,%4};"
                 :: "l"(dstp), "f"(v.x), "f"(v.y), "f"(v.z), "f"(v.w)
                 : "memory");
    if (lane == 0) atomicAdd(&g_deg[d], 1.0f);
}

// ---------------- fused SGEMM: out = [mean|h] @ Wc + bias (optionally relu) ----------------
// 128x128 tile, BK=8, 256 threads, 8x8 register tile.
template <int KTOT, bool SAGE, bool RELU>
__global__ void __launch_bounds__(256)
gemm_kernel(const float* __restrict__ A, const float* __restrict__ Wc,
            const float* __restrict__ bias, float* __restrict__ out) {
    __shared__ __align__(16) float As[8][C];
    __shared__ __align__(16) float Bs[8][C];
    int tid = threadIdx.x;
    int tx = tid & 15;       // col group
    int ty = tid >> 4;       // row group
    int row0 = blockIdx.x * C;

    // A-load mapping: 1024 elems/tile = 128 rows x 8 k, 4 per thread
    int a_row = tid >> 1;
    int a_k = (tid & 1) * 4;
    // B-load mapping: 1024 elems/tile = 8 k x 128 cols, 4 per thread
    int b_k = tid >> 5;
    int b_col = (tid & 31) * 4;

    int grow = row0 + a_row;
    float rd = 0.f;
    if (SAGE) {
        if (grow < N_NODES) rd = 1.0f / fmaxf(g_deg[grow], 1.0f);
    }

    float acc[8][8];
#pragma unroll
    for (int i = 0; i < 8; i++)
#pragma unroll
        for (int j = 0; j < 8; j++) acc[i][j] = 0.f;

    for (int kt = 0; kt < KTOT; kt += 8) {
        float4 av = make_float4(0.f, 0.f, 0.f, 0.f);
        if (grow < N_NODES) {
            int gk = kt + a_k;
            if (SAGE) {
                if (gk < C) {
                    float4 t = *reinterpret_cast<const float4*>(g_agg + (size_t)grow * C + gk);
                    av = make_float4(t.x * rd, t.y * rd, t.z * rd, t.w * rd);
                } else {
                    av = *reinterpret_cast<const float4*>(A + (size_t)grow * C + (gk - C));
                }
            } else {
                av = *reinterpret_cast<const float4*>(A + (size_t)grow * C + gk);
            }
        }
        As[a_k + 0][a_row] = av.x;
        As[a_k + 1][a_row] = av.y;
        As[a_k + 2][a_row] = av.z;
        As[a_k + 3][a_row] = av.w;
        *reinterpret_cast<float4*>(&Bs[b_k][b_col]) =
            *reinterpret_cast<const float4*>(Wc + (size_t)(kt + b_k) * C + b_col);
        __syncthreads();
#pragma unroll
        for (int kk = 0; kk < 8; kk++) {
            float a[8], b[8];
            *reinterpret_cast<float4*>(&a[0]) = *reinterpret_cast<const float4*>(&As[kk][ty * 8]);
            *reinterpret_cast<float4*>(&a[4]) = *reinterpret_cast<const float4*>(&As[kk][ty * 8 + 4]);
            *reinterpret_cast<float4*>(&b[0]) = *reinterpret_cast<const float4*>(&Bs[kk][tx * 8]);
            *reinterpret_cast<float4*>(&b[4]) = *reinterpret_cast<const float4*>(&Bs[kk][tx * 8 + 4]);
#pragma unroll
            for (int i = 0; i < 8; i++)
#pragma unroll
                for (int j = 0; j < 8; j++) acc[i][j] += a[i] * b[j];
        }
        __syncthreads();
    }

    // epilogue
#pragma unroll
    for (int i = 0; i < 8; i++) {
        int row = row0 + ty * 8 + i;
        if (row >= N_NODES) continue;
#pragma unroll
        for (int j = 0; j < 8; j += 4) {
            int col = tx * 8 + j;
            float4 v;
            v.x = acc[i][j + 0] + bias[col + 0];
            v.y = acc[i][j + 1] + bias[col + 1];
            v.z = acc[i][j + 2] + bias[col + 2];
            v.w = acc[i][j + 3] + bias[col + 3];
            if (RELU) {
                v.x = fmaxf(v.x, 0.f); v.y = fmaxf(v.y, 0.f);
                v.z = fmaxf(v.z, 0.f); v.w = fmaxf(v.w, 0.f);
            }
            *reinterpret_cast<float4*>(out + (size_t)row * C + col) = v;
        }
    }
}

// ---------------- BN statistics (per-channel sum / sumsq) ----------------
__global__ void stats_kernel(const float* __restrict__ h) {
    __shared__ float ss[256], sq[256];
    int tid = threadIdx.x;
    int c = tid & (C - 1);
    int half = tid >> 7;
    float s = 0.f, q = 0.f;
    for (int row = blockIdx.x * 2 + half; row < N_NODES; row += gridDim.x * 2) {
        float v = h[(size_t)row * C + c];
        s += v;
        q += v * v;
    }
    ss[tid] = s;
    sq[tid] = q;
    __syncthreads();
    if (tid < C) {
        atomicAdd(&g_sum[c], ss[tid] + ss[tid + C]);
        atomicAdd(&g_sumsq[c], sq[tid] + sq[tid + C]);
    }
}

__global__ void bnparam_kernel(const float* __restrict__ g, const float* __restrict__ be) {
    int c = threadIdx.x;
    if (c >= C) return;
    float m = g_sum[c] / (float)N_NODES;
    float v = g_sumsq[c] / (float)N_NODES - m * m;
    float sc = g[c] * rsqrtf(fmaxf(v, 0.f) + EPS_BN);
    g_scale[c] = sc;
    g_shift[c] = be[c] - m * sc;
}

__global__ void bnrelu_kernel(float* __restrict__ h) {
    int stride = gridDim.x * blockDim.x;
    for (int idx = blockIdx.x * blockDim.x + threadIdx.x; idx < N_NODES * (C / 4); idx += stride) {
        int c = (idx & (C / 4 - 1)) * 4;
        float4* p = reinterpret_cast<float4*>(h) + idx;
        float4 v = *p;
        v.x = fmaxf(v.x * g_scale[c + 0] + g_shift[c + 0], 0.f);
        v.y = fmaxf(v.y * g_scale[c + 1] + g_shift[c + 1], 0.f);
        v.z = fmaxf(v.z * g_scale[c + 2] + g_shift[c + 2], 0.f);
        v.w = fmaxf(v.w * g_scale[c + 3] + g_shift[c + 3], 0.f);
        *p = v;
    }
}

// ---------------- head-2: warp-per-row dot with 2 output columns ----------------
__global__ void head2_kernel(const float* __restrict__ h, const float* __restrict__ Wh2,
                             const float* __restrict__ bh2, float* __restrict__ out) {
    int gtid = blockIdx.x * blockDim.x + threadIdx.x;
    int w = gtid >> 5;
    int lane = gtid & 31;
    if (w >= N_NODES) return;
    float2 v = *reinterpret_cast<const float2*>(h + (size_t)w * C + lane * 2);
    float s0 = v.x * Wh2[lane * 2] + v.y * Wh2[lane * 2 + 1];
    float s1 = v.x * Wh2[64 + lane * 2] + v.y * Wh2[64 + lane * 2 + 1];
#pragma unroll
    for (int o = 16; o > 0; o >>= 1) {
        s0 += __shfl_down_sync(0xffffffffu, s0, o);
        s1 += __shfl_down_sync(0xffffffffu, s1, o);
    }
    if (lane == 0) {
        out[(size_t)w * 2 + 0] = s0 + bh2[0];
        out[(size_t)w * 2 + 1] = s1 + bh2[1];
    }
}

// ---------------- launch ----------------
extern "C" void kernel_launch(void* const* d_in, const int* in_sizes, int n_in,
                              void* d_out, int out_size) {
    const float* x = (const float*)d_in[0];
    const int* ei32 = (const int*)d_in[1];
    const float* Wn[3] = {(const float*)d_in[2], (const float*)d_in[7], (const float*)d_in[12]};
    const float* bn[3] = {(const float*)d_in[3], (const float*)d_in[8], (const float*)d_in[13]};
    const float* Wr[3] = {(const float*)d_in[4], (const float*)d_in[9], (const float*)d_in[14]};
    const float* ga[3] = {(const float*)d_in[5], (const float*)d_in[10], (const float*)d_in[15]};
    const float* be[3] = {(const float*)d_in[6], (const float*)d_in[11], (const float*)d_in[16]};
    const float* Wh1 = (const float*)d_in[17];
    const float* bh1 = (const float*)d_in[18];
    const float* Wh2 = (const float*)d_in[19];
    const float* bh2 = (const float*)d_in[20];
    float* out = (float*)d_out;

    float *p_h1, *p_h2, *p_Wc, *p_Wh1p, *p_bh1p;
    cudaGetSymbolAddress((void**)&p_h1, g_h1);
    cudaGetSymbolAddress((void**)&p_h2, g_h2);
    cudaGetSymbolAddress((void**)&p_Wc, g_Wc);
    cudaGetSymbolAddress((void**)&p_Wh1p, g_Wh1p);
    cudaGetSymbolAddress((void**)&p_bh1p, g_bh1p);

    // edge decode (dtype-agnostic)
    detect_kernel<<<1, 256>>>(ei32);
    decode_kernel<<<(N_EDGES + 255) / 256, 256>>>(ei32);

    // pack weights
    for (int l = 0; l < 3; l++)
        pack_pair_kernel<<<(2 * C * C + 255) / 256, 256>>>(Wn[l], Wr[l], l);
    pack_head_kernel<<<(C * C + 255) / 256, 256>>>(Wh1, bh1);

    const int gemm_blocks = (N_NODES + 127) / 128;
    const float* h_in = x;
    float* h_out = p_h1;
    float* bufs[2] = {p_h1, p_h2};

    for (int l = 0; l < 3; l++) {
        h_out = bufs[l & 1];
        zero_kernel<<<2048, 256>>>();
        scatter_kernel<<<(N_EDGES * 32 + 255) / 256, 256>>>(h_in);
        gemm_kernel<2 * C, true, false><<<gemm_blocks, 256>>>(
            h_in, p_Wc + (size_t)l * 2 * C * C, bn[l], h_out);
        stats_kernel<<<512, 256>>>(h_out);
        bnparam_kernel<<<1, 128>>>(ga[l], be[l]);
        bnrelu_kernel<<<2048, 256>>>(h_out);
        h_in = h_out;
    }

    // head: layer-2 output lives in bufs[0]=g_h1 -> g_h2 (padded 128 cols) -> out
    gemm_kernel<C, false, true><<<gemm_blocks, 256>>>(p_h1, p_Wh1p, p_bh1p, p_h2);
    head2_kernel<<<(N_NODES * 32 + 255) / 256, 256>>>(p_h2, Wh2, bh2, out);
}

// round 3
// speedup vs baseline: 1.1093x; 1.1093x over previous
#include <cuda_runtime.h>
#include <cstdint>

#define N_NODES 100000
#define N_EDGES 800000
#define C 128
#define EPS_BN 1e-5f

// ---------------- device scratch (no allocs allowed) ----------------
__device__ float g_agg[N_NODES * C];        // 51.2 MB
__device__ float g_deg[N_NODES];
__device__ float g_h1[N_NODES * C];         // 51.2 MB
__device__ float g_h2[N_NODES * C];         // 51.2 MB
__device__ float g_Wc[3][2 * C * C];        // packed [K=256][128] per layer
__device__ float g_Wh1p[C * C];             // padded head-1 weights [K=128][128]
__device__ float g_bh1p[C];
__device__ float g_sum[C];
__device__ float g_sumsq[C];
__device__ float g_scale[C];
__device__ float g_shift[C];
__device__ int g_src[N_EDGES];
__device__ int g_dst[N_EDGES];
__device__ int g_is64;

// ---------------- edge dtype detection + decode ----------------
// int64 edge_index => high word of every element is 0 (indices < 1e5).
__global__ void detect_kernel(const int* __restrict__ w) {
    __shared__ int acc[256];
    int tid = threadIdx.x;
    int v = 0;
    for (int i = tid; i < 1024; i += 256) v |= w[2 * i + 1];
    acc[tid] = v;
    __syncthreads();
    for (int s = 128; s > 0; s >>= 1) {
        if (tid < s) acc[tid] |= acc[tid + s];
        __syncthreads();
    }
    if (tid == 0) g_is64 = (acc[0] == 0) ? 1 : 0;
}

__global__ void decode_kernel(const int* __restrict__ w) {
    int e = blockIdx.x * blockDim.x + threadIdx.x;
    if (e >= N_EDGES) return;
    if (g_is64) {
        g_src[e] = w[2 * e];
        g_dst[e] = w[2 * (N_EDGES + e)];
    } else {
        g_src[e] = w[e];
        g_dst[e] = w[N_EDGES + e];
    }
}

// ---------------- prep: pack all weights (single launch) ----------------
__global__ void pack_all_kernel(const float* __restrict__ Wn0, const float* __restrict__ Wr0,
                                const float* __restrict__ Wn1, const float* __restrict__ Wr1,
                                const float* __restrict__ Wn2, const float* __restrict__ Wr2) {
    int idx = blockIdx.x * blockDim.x + threadIdx.x;
    if (idx >= 3 * 2 * C * C) return;
    int layer = idx / (2 * C * C);
    int r = idx % (2 * C * C);
    int k = r / C, j = r % C;
    const float* Wn = (layer == 0) ? Wn0 : (layer == 1) ? Wn1 : Wn2;
    const float* Wr = (layer == 0) ? Wr0 : (layer == 1) ? Wr1 : Wr2;
    g_Wc[layer][r] = (k < C) ? Wn[j * C + k] : Wr[j * C + (k - C)];
}

__global__ void pack_head_kernel(const float* __restrict__ Wh1,
                                 const float* __restrict__ bh1) {
    int idx = blockIdx.x * blockDim.x + threadIdx.x;
    if (idx < C * C) {
        int k = idx / C, j = idx % C;
        g_Wh1p[idx] = (j < 64) ? Wh1[j * C + k] : 0.0f;
    }
    if (idx < C) g_bh1p[idx] = (idx < 64) ? bh1[idx] : 0.0f;
}

// ---------------- zero agg/deg/stats ----------------
__global__ void zero_kernel() {
    int stride = gridDim.x * blockDim.x;
    float4 z = make_float4(0.f, 0.f, 0.f, 0.f);
    for (int i = blockIdx.x * blockDim.x + threadIdx.x; i < N_NODES * C / 4; i += stride) {
        reinterpret_cast<float4*>(g_agg)[i] = z;
        if (i < N_NODES / 4) reinterpret_cast<float4*>(g_deg)[i] = z;
        if (i < C) { g_sum[i] = 0.f; g_sumsq[i] = 0.f; }
    }
}

// ---------------- edge scatter: warp per edge, fused BN+ReLU on gather ----------------
template <bool XFORM>
__global__ void scatter_kernel(const float* __restrict__ h) {
    int gtid = blockIdx.x * blockDim.x + threadIdx.x;
    int e = gtid >> 5;
    int lane = gtid & 31;
    if (e >= N_EDGES) return;
    int s = g_src[e];
    int d = g_dst[e];
    float4 v = *reinterpret_cast<const float4*>(h + (size_t)s * C + lane * 4);
    if (XFORM) {
        float4 sc = reinterpret_cast<const float4*>(g_scale)[lane];
        float4 sh = reinterpret_cast<const float4*>(g_shift)[lane];
        v.x = fmaxf(v.x * sc.x + sh.x, 0.f);
        v.y = fmaxf(v.y * sc.y + sh.y, 0.f);
        v.z = fmaxf(v.z * sc.z + sh.z, 0.f);
        v.w = fmaxf(v.w * sc.w + sh.w, 0.f);
    }
    float* dstp = g_agg + (size_t)d * C + lane * 4;
    asm volatile("red.global.add.v4.f32 [%0], {%1,%2,%3,%4};"
                 :: "l"(dstp), "f"(v.x), "f"(v.y), "f"(v.z), "f"(v.w)
                 : "memory");
    if (lane == 0) atomicAdd(&g_deg[d], 1.0f);
}

// ---------------- fused SGEMM ----------------
// out = [mean | f(h)] @ Wc + bias  where f = BN+ReLU transform (if XFORM).
// Optionally accumulates per-column sum/sumsq (STATS) or applies output relu (RELU_OUT).
template <int KTOT, bool SAGE, bool XFORM, bool RELU_OUT, bool STATS>
__global__ void __launch_bounds__(256)
gemm_kernel(const float* __restrict__ A, const float* __restrict__ Wc,
            const float* __restrict__ bias, float* __restrict__ out) {
    __shared__ __align__(16) float As[8][C];
    __shared__ __align__(16) float Bs[8][C];
    __shared__ float s_sum[16][C];
    __shared__ float s_sq[16][C];
    int tid = threadIdx.x;
    int tx = tid & 15;       // col group
    int ty = tid >> 4;       // row group
    int row0 = blockIdx.x * C;

    int a_row = tid >> 1;
    int a_k = (tid & 1) * 4;
    int b_k = tid >> 5;
    int b_col = (tid & 31) * 4;

    int grow = row0 + a_row;
    float rd = 0.f;
    if (SAGE && grow < N_NODES) rd = 1.0f / fmaxf(g_deg[grow], 1.0f);

    float acc[8][8];
#pragma unroll
    for (int i = 0; i < 8; i++)
#pragma unroll
        for (int j = 0; j < 8; j++) acc[i][j] = 0.f;

    // A tile loader
    auto load_a = [&](int kt) -> float4 {
        float4 av = make_float4(0.f, 0.f, 0.f, 0.f);
        if (grow < N_NODES) {
            int gk = kt + a_k;
            if (SAGE && gk < C) {
                float4 t = *reinterpret_cast<const float4*>(g_agg + (size_t)grow * C + gk);
                av = make_float4(t.x * rd, t.y * rd, t.z * rd, t.w * rd);
            } else {
                int col = SAGE ? gk - C : gk;
                av = *reinterpret_cast<const float4*>(A + (size_t)grow * C + col);
                if (XFORM) {
                    av.x = fmaxf(av.x * g_scale[col + 0] + g_shift[col + 0], 0.f);
                    av.y = fmaxf(av.y * g_scale[col + 1] + g_shift[col + 1], 0.f);
                    av.z = fmaxf(av.z * g_scale[col + 2] + g_shift[col + 2], 0.f);
                    av.w = fmaxf(av.w * g_scale[col + 3] + g_shift[col + 3], 0.f);
                }
            }
        }
        return av;
    };

    float4 na = load_a(0);
    float4 nb = *reinterpret_cast<const float4*>(Wc + (size_t)b_k * C + b_col);

    for (int kt = 0; kt < KTOT; kt += 8) {
        As[a_k + 0][a_row] = na.x;
        As[a_k + 1][a_row] = na.y;
        As[a_k + 2][a_row] = na.z;
        As[a_k + 3][a_row] = na.w;
        *reinterpret_cast<float4*>(&Bs[b_k][b_col]) = nb;
        __syncthreads();
        if (kt + 8 < KTOT) {
            na = load_a(kt + 8);
            nb = *reinterpret_cast<const float4*>(Wc + (size_t)(kt + 8 + b_k) * C + b_col);
        }
#pragma unroll
        for (int kk = 0; kk < 8; kk++) {
            float a[8], b[8];
            *reinterpret_cast<float4*>(&a[0]) = *reinterpret_cast<const float4*>(&As[kk][ty * 8]);
            *reinterpret_cast<float4*>(&a[4]) = *reinterpret_cast<const float4*>(&As[kk][ty * 8 + 4]);
            *reinterpret_cast<float4*>(&b[0]) = *reinterpret_cast<const float4*>(&Bs[kk][tx * 8]);
            *reinterpret_cast<float4*>(&b[4]) = *reinterpret_cast<const float4*>(&Bs[kk][tx * 8 + 4]);
#pragma unroll
            for (int i = 0; i < 8; i++)
#pragma unroll
                for (int j = 0; j < 8; j++) acc[i][j] += a[i] * b[j];
        }
        __syncthreads();
    }

    // epilogue
    float psum[8], psq[8];
#pragma unroll
    for (int j = 0; j < 8; j++) { psum[j] = 0.f; psq[j] = 0.f; }

#pragma unroll
    for (int i = 0; i < 8; i++) {
        int row = row0 + ty * 8 + i;
        if (row >= N_NODES) continue;
#pragma unroll
        for (int j = 0; j < 8; j += 4) {
            int col = tx * 8 + j;
            float4 v;
            v.x = acc[i][j + 0] + bias[col + 0];
            v.y = acc[i][j + 1] + bias[col + 1];
            v.z = acc[i][j + 2] + bias[col + 2];
            v.w = acc[i][j + 3] + bias[col + 3];
            if (RELU_OUT) {
                v.x = fmaxf(v.x, 0.f); v.y = fmaxf(v.y, 0.f);
                v.z = fmaxf(v.z, 0.f); v.w = fmaxf(v.w, 0.f);
            }
            if (STATS) {
                psum[j + 0] += v.x; psq[j + 0] += v.x * v.x;
                psum[j + 1] += v.y; psq[j + 1] += v.y * v.y;
                psum[j + 2] += v.z; psq[j + 2] += v.z * v.z;
                psum[j + 3] += v.w; psq[j + 3] += v.w * v.w;
            }
            *reinterpret_cast<float4*>(out + (size_t)row * C + col) = v;
        }
    }

    if (STATS) {
#pragma unroll
        for (int j = 0; j < 8; j++) {
            s_sum[ty][tx * 8 + j] = psum[j];
            s_sq[ty][tx * 8 + j] = psq[j];
        }
        __syncthreads();
        if (tid < C) {
            float s = 0.f, q = 0.f;
#pragma unroll
            for (int t = 0; t < 16; t++) { s += s_sum[t][tid]; q += s_sq[t][tid]; }
            atomicAdd(&g_sum[tid], s);
            atomicAdd(&g_sumsq[tid], q);
        }
    }
}

__global__ void bnparam_kernel(const float* __restrict__ g, const float* __restrict__ be) {
    int c = threadIdx.x;
    if (c >= C) return;
    float m = g_sum[c] / (float)N_NODES;
    float v = g_sumsq[c] / (float)N_NODES - m * m;
    float sc = g[c] * rsqrtf(fmaxf(v, 0.f) + EPS_BN);
    g_scale[c] = sc;
    g_shift[c] = be[c] - m * sc;
}

// ---------------- head-2: warp-per-row dot with 2 output columns ----------------
__global__ void head2_kernel(const float* __restrict__ h, const float* __restrict__ Wh2,
                             const float* __restrict__ bh2, float* __restrict__ out) {
    int gtid = blockIdx.x * blockDim.x + threadIdx.x;
    int w = gtid >> 5;
    int lane = gtid & 31;
    if (w >= N_NODES) return;
    float2 v = *reinterpret_cast<const float2*>(h + (size_t)w * C + lane * 2);
    float s0 = v.x * Wh2[lane * 2] + v.y * Wh2[lane * 2 + 1];
    float s1 = v.x * Wh2[64 + lane * 2] + v.y * Wh2[64 + lane * 2 + 1];
#pragma unroll
    for (int o = 16; o > 0; o >>= 1) {
        s0 += __shfl_down_sync(0xffffffffu, s0, o);
        s1 += __shfl_down_sync(0xffffffffu, s1, o);
    }
    if (lane == 0) {
        out[(size_t)w * 2 + 0] = s0 + bh2[0];
        out[(size_t)w * 2 + 1] = s1 + bh2[1];
    }
}

// ---------------- launch ----------------
extern "C" void kernel_launch(void* const* d_in, const int* in_sizes, int n_in,
                              void* d_out, int out_size) {
    const float* x = (const float*)d_in[0];
    const int* ei32 = (const int*)d_in[1];
    const float* Wn[3] = {(const float*)d_in[2], (const float*)d_in[7], (const float*)d_in[12]};
    const float* bn[3] = {(const float*)d_in[3], (const float*)d_in[8], (const float*)d_in[13]};
    const float* Wr[3] = {(const float*)d_in[4], (const float*)d_in[9], (const float*)d_in[14]};
    const float* ga[3] = {(const float*)d_in[5], (const float*)d_in[10], (const float*)d_in[15]};
    const float* be[3] = {(const float*)d_in[6], (const float*)d_in[11], (const float*)d_in[16]};
    const float* Wh1 = (const float*)d_in[17];
    const float* bh1 = (const float*)d_in[18];
    const float* Wh2 = (const float*)d_in[19];
    const float* bh2 = (const float*)d_in[20];
    float* out = (float*)d_out;

    float *p_h1, *p_h2, *p_Wc, *p_Wh1p, *p_bh1p;
    cudaGetSymbolAddress((void**)&p_h1, g_h1);
    cudaGetSymbolAddress((void**)&p_h2, g_h2);
    cudaGetSymbolAddress((void**)&p_Wc, g_Wc);
    cudaGetSymbolAddress((void**)&p_Wh1p, g_Wh1p);
    cudaGetSymbolAddress((void**)&p_bh1p, g_bh1p);

    // launches 0-4 (ncu -s 5 -c 1 then profiles launch #5 = layer-0 scatter)
    detect_kernel<<<1, 256>>>(ei32);                                        // 0
    decode_kernel<<<(N_EDGES + 255) / 256, 256>>>(ei32);                    // 1
    pack_all_kernel<<<(3 * 2 * C * C + 255) / 256, 256>>>(
        Wn[0], Wr[0], Wn[1], Wr[1], Wn[2], Wr[2]);                          // 2
    pack_head_kernel<<<(C * C + 255) / 256, 256>>>(Wh1, bh1);               // 3

    const int gemm_blocks = (N_NODES + 127) / 128;
    const int scat_blocks = (N_EDGES * 32 + 255) / 256;
    float* bufs[2] = {p_h1, p_h2};
    const float* h_in = x;

    for (int l = 0; l < 3; l++) {
        float* h_out = bufs[l & 1];
        zero_kernel<<<2048, 256>>>();                                       // 4 (l=0)
        if (l == 0) {
            scatter_kernel<false><<<scat_blocks, 256>>>(h_in);              // 5 <- profiled
            gemm_kernel<2 * C, true, false, false, true><<<gemm_blocks, 256>>>(
                h_in, p_Wc, bn[l], h_out);
        } else {
            scatter_kernel<true><<<scat_blocks, 256>>>(h_in);
            gemm_kernel<2 * C, true, true, false, true><<<gemm_blocks, 256>>>(
                h_in, p_Wc + (size_t)l * 2 * C * C, bn[l], h_out);
        }
        bnparam_kernel<<<1, 128>>>(ga[l], be[l]);
        h_in = h_out;
    }

    // head: layer-2 raw output is in bufs[0]=g_h1; apply its BN+ReLU on load.
    gemm_kernel<C, false, true, true, false><<<gemm_blocks, 256>>>(
        p_h1, p_Wh1p, p_bh1p, p_h2);
    head2_kernel<<<(N_NODES * 32 + 255) / 256, 256>>>(p_h2, Wh2, bh2, out);
}

// round 4
// speedup vs baseline: 1.1244x; 1.0136x over previous
#include <cuda_runtime.h>
#include <cstdint>

#define N_NODES 100000
#define N_EDGES 800000
#define C 128
#define EPS_BN 1e-5f

// ---------------- device scratch (no allocs allowed) ----------------
__device__ float g_agg[N_NODES * C];        // 51.2 MB
__device__ float g_deg[N_NODES];
__device__ float g_h1[N_NODES * C];         // 51.2 MB
__device__ float g_h2[N_NODES * C];         // 51.2 MB
__device__ float g_Wc[3][2 * C * C];        // packed [K=256][128] per layer
__device__ float g_Wh1p[C * C];             // padded head-1 weights [K=128][128]
__device__ float g_bh1p[C];
__device__ float g_sum[C];
__device__ float g_sumsq[C];
__device__ float g_scale[C];
__device__ float g_shift[C];
__device__ int g_src[N_EDGES];
__device__ int g_dst[N_EDGES];
__device__ int g_is64;

// ---------------- f32x2 packed helpers ----------------
__device__ __forceinline__ unsigned long long pk2(float x, float y) {
    unsigned long long r;
    asm("mov.b64 %0, {%1, %2};" : "=l"(r) : "f"(x), "f"(y));
    return r;
}
__device__ __forceinline__ void unpk2(unsigned long long v, float& x, float& y) {
    asm("mov.b64 {%0, %1}, %2;" : "=f"(x), "=f"(y) : "l"(v));
}
__device__ __forceinline__ void fma2(unsigned long long& d, unsigned long long a,
                                     unsigned long long b) {
    asm("fma.rn.f32x2 %0, %1, %2, %0;" : "+l"(d) : "l"(a), "l"(b));
}

// ---------------- edge dtype detection + decode ----------------
__global__ void detect_kernel(const int* __restrict__ w) {
    __shared__ int acc[256];
    int tid = threadIdx.x;
    int v = 0;
    for (int i = tid; i < 1024; i += 256) v |= w[2 * i + 1];
    acc[tid] = v;
    __syncthreads();
    for (int s = 128; s > 0; s >>= 1) {
        if (tid < s) acc[tid] |= acc[tid + s];
        __syncthreads();
    }
    if (tid == 0) g_is64 = (acc[0] == 0) ? 1 : 0;
}

__global__ void decode_kernel(const int* __restrict__ w) {
    int e = blockIdx.x * blockDim.x + threadIdx.x;
    if (e >= N_EDGES) return;
    if (g_is64) {
        g_src[e] = w[2 * e];
        g_dst[e] = w[2 * (N_EDGES + e)];
    } else {
        g_src[e] = w[e];
        g_dst[e] = w[N_EDGES + e];
    }
}

// ---------------- prep: pack all weights (single launch) ----------------
__global__ void pack_all_kernel(const float* __restrict__ Wn0, const float* __restrict__ Wr0,
                                const float* __restrict__ Wn1, const float* __restrict__ Wr1,
                                const float* __restrict__ Wn2, const float* __restrict__ Wr2) {
    int idx = blockIdx.x * blockDim.x + threadIdx.x;
    if (idx >= 3 * 2 * C * C) return;
    int layer = idx / (2 * C * C);
    int r = idx % (2 * C * C);
    int k = r / C, j = r % C;
    const float* Wn = (layer == 0) ? Wn0 : (layer == 1) ? Wn1 : Wn2;
    const float* Wr = (layer == 0) ? Wr0 : (layer == 1) ? Wr1 : Wr2;
    g_Wc[layer][r] = (k < C) ? Wn[j * C + k] : Wr[j * C + (k - C)];
}

__global__ void pack_head_kernel(const float* __restrict__ Wh1,
                                 const float* __restrict__ bh1) {
    int idx = blockIdx.x * blockDim.x + threadIdx.x;
    if (idx < C * C) {
        int k = idx / C, j = idx % C;
        g_Wh1p[idx] = (j < 64) ? Wh1[j * C + k] : 0.0f;
    }
    if (idx < C) g_bh1p[idx] = (idx < 64) ? bh1[idx] : 0.0f;
}

// ---------------- zero agg (+deg optionally) + stats ----------------
template <bool ZDEG>
__global__ void zero_kernel() {
    int stride = gridDim.x * blockDim.x;
    float4 z = make_float4(0.f, 0.f, 0.f, 0.f);
    for (int i = blockIdx.x * blockDim.x + threadIdx.x; i < N_NODES * C / 4; i += stride) {
        reinterpret_cast<float4*>(g_agg)[i] = z;
        if (ZDEG && i < N_NODES / 4) reinterpret_cast<float4*>(g_deg)[i] = z;
        if (i < C) { g_sum[i] = 0.f; g_sumsq[i] = 0.f; }
    }
}

// ---------------- edge scatter: warp per edge, fused BN+ReLU on gather ----------------
// DEG: also count degrees (first layer only — graph is constant across layers).
template <bool XFORM, bool DEG>
__global__ void scatter_kernel(const float* __restrict__ h) {
    int gtid = blockIdx.x * blockDim.x + threadIdx.x;
    int e = gtid >> 5;
    int lane = gtid & 31;
    if (e >= N_EDGES) return;
    int s = g_src[e];
    int d = g_dst[e];
    float4 v = *reinterpret_cast<const float4*>(h + (size_t)s * C + lane * 4);
    if (XFORM) {
        float4 sc = reinterpret_cast<const float4*>(g_scale)[lane];
        float4 sh = reinterpret_cast<const float4*>(g_shift)[lane];
        v.x = fmaxf(v.x * sc.x + sh.x, 0.f);
        v.y = fmaxf(v.y * sc.y + sh.y, 0.f);
        v.z = fmaxf(v.z * sc.z + sh.z, 0.f);
        v.w = fmaxf(v.w * sc.w + sh.w, 0.f);
    }
    float* dstp = g_agg + (size_t)d * C + lane * 4;
    asm volatile("red.global.add.v4.f32 [%0], {%1,%2,%3,%4};"
                 :: "l"(dstp), "f"(v.x), "f"(v.y), "f"(v.z), "f"(v.w)
                 : "memory");
    if (DEG && lane == 0) atomicAdd(&g_deg[d], 1.0f);
}

// ---------------- fused SGEMM (f32x2 packed FMA inner loop) ----------------
template <int KTOT, bool SAGE, bool XFORM, bool RELU_OUT, bool STATS>
__global__ void __launch_bounds__(256)
gemm_kernel(const float* __restrict__ A, const float* __restrict__ Wc,
            const float* __restrict__ bias, float* __restrict__ out) {
    __shared__ __align__(16) float As[8][C];
    __shared__ __align__(16) float Bs[8][C];
    __shared__ float s_sum[16][C];
    __shared__ float s_sq[16][C];
    int tid = threadIdx.x;
    int tx = tid & 15;       // col group
    int ty = tid >> 4;       // row group
    int row0 = blockIdx.x * C;

    int a_row = tid >> 1;
    int a_k = (tid & 1) * 4;
    int b_k = tid >> 5;
    int b_col = (tid & 31) * 4;

    int grow = row0 + a_row;
    float rd = 0.f;
    if (SAGE && grow < N_NODES) rd = 1.0f / fmaxf(g_deg[grow], 1.0f);

    // packed accumulators: acc2[i][j2] holds cols (2*j2, 2*j2+1) for row i
    unsigned long long acc2[8][4];
#pragma unroll
    for (int i = 0; i < 8; i++)
#pragma unroll
        for (int j = 0; j < 4; j++) acc2[i][j] = 0ull;

    auto load_a = [&](int kt) -> float4 {
        float4 av = make_float4(0.f, 0.f, 0.f, 0.f);
        if (grow < N_NODES) {
            int gk = kt + a_k;
            if (SAGE && gk < C) {
                float4 t = *reinterpret_cast<const float4*>(g_agg + (size_t)grow * C + gk);
                av = make_float4(t.x * rd, t.y * rd, t.z * rd, t.w * rd);
            } else {
                int col = SAGE ? gk - C : gk;
                av = *reinterpret_cast<const float4*>(A + (size_t)grow * C + col);
                if (XFORM) {
                    av.x = fmaxf(av.x * g_scale[col + 0] + g_shift[col + 0], 0.f);
                    av.y = fmaxf(av.y * g_scale[col + 1] + g_shift[col + 1], 0.f);
                    av.z = fmaxf(av.z * g_scale[col + 2] + g_shift[col + 2], 0.f);
                    av.w = fmaxf(av.w * g_scale[col + 3] + g_shift[col + 3], 0.f);
                }
            }
        }
        return av;
    };

    float4 na = load_a(0);
    float4 nb = *reinterpret_cast<const float4*>(Wc + (size_t)b_k * C + b_col);

    for (int kt = 0; kt < KTOT; kt += 8) {
        As[a_k + 0][a_row] = na.x;
        As[a_k + 1][a_row] = na.y;
        As[a_k + 2][a_row] = na.z;
        As[a_k + 3][a_row] = na.w;
        *reinterpret_cast<float4*>(&Bs[b_k][b_col]) = nb;
        __syncthreads();
        if (kt + 8 < KTOT) {
            na = load_a(kt + 8);
            nb = *reinterpret_cast<const float4*>(Wc + (size_t)(kt + 8 + b_k) * C + b_col);
        }
#pragma unroll
        for (int kk = 0; kk < 8; kk++) {
            float a[8];
            unsigned long long b2[4];
            *reinterpret_cast<float4*>(&a[0]) = *reinterpret_cast<const float4*>(&As[kk][ty * 8]);
            *reinterpret_cast<float4*>(&a[4]) = *reinterpret_cast<const float4*>(&As[kk][ty * 8 + 4]);
            *reinterpret_cast<ulonglong2*>(&b2[0]) =
                *reinterpret_cast<const ulonglong2*>(&Bs[kk][tx * 8]);
            *reinterpret_cast<ulonglong2*>(&b2[2]) =
                *reinterpret_cast<const ulonglong2*>(&Bs[kk][tx * 8 + 4]);
#pragma unroll
            for (int i = 0; i < 8; i++) {
                unsigned long long ad = pk2(a[i], a[i]);
#pragma unroll
                for (int j = 0; j < 4; j++) fma2(acc2[i][j], ad, b2[j]);
            }
        }
        __syncthreads();
    }

    // epilogue
    float psum[8], psq[8];
#pragma unroll
    for (int j = 0; j < 8; j++) { psum[j] = 0.f; psq[j] = 0.f; }

#pragma unroll
    for (int i = 0; i < 8; i++) {
        int row = row0 + ty * 8 + i;
        if (row >= N_NODES) continue;
        float accf[8];
#pragma unroll
        for (int j = 0; j < 4; j++) unpk2(acc2[i][j], accf[2 * j], accf[2 * j + 1]);
#pragma unroll
        for (int j = 0; j < 8; j += 4) {
            int col = tx * 8 + j;
            float4 v;
            v.x = accf[j + 0] + bias[col + 0];
            v.y = accf[j + 1] + bias[col + 1];
            v.z = accf[j + 2] + bias[col + 2];
            v.w = accf[j + 3] + bias[col + 3];
            if (RELU_OUT) {
                v.x = fmaxf(v.x, 0.f); v.y = fmaxf(v.y, 0.f);
                v.z = fmaxf(v.z, 0.f); v.w = fmaxf(v.w, 0.f);
            }
            if (STATS) {
                psum[j + 0] += v.x; psq[j + 0] += v.x * v.x;
                psum[j + 1] += v.y; psq[j + 1] += v.y * v.y;
                psum[j + 2] += v.z; psq[j + 2] += v.z * v.z;
                psum[j + 3] += v.w; psq[j + 3] += v.w * v.w;
            }
            *reinterpret_cast<float4*>(out + (size_t)row * C + col) = v;
        }
    }

    if (STATS) {
#pragma unroll
        for (int j = 0; j < 8; j++) {
            s_sum[ty][tx * 8 + j] = psum[j];
            s_sq[ty][tx * 8 + j] = psq[j];
        }
        __syncthreads();
        if (tid < C) {
            float s = 0.f, q = 0.f;
#pragma unroll
            for (int t = 0; t < 16; t++) { s += s_sum[t][tid]; q += s_sq[t][tid]; }
            atomicAdd(&g_sum[tid], s);
            atomicAdd(&g_sumsq[tid], q);
        }
    }
}

__global__ void bnparam_kernel(const float* __restrict__ g, const float* __restrict__ be) {
    int c = threadIdx.x;
    if (c >= C) return;
    float m = g_sum[c] / (float)N_NODES;
    float v = g_sumsq[c] / (float)N_NODES - m * m;
    float sc = g[c] * rsqrtf(fmaxf(v, 0.f) + EPS_BN);
    g_scale[c] = sc;
    g_shift[c] = be[c] - m * sc;
}

// ---------------- head-2: warp-per-row dot with 2 output columns ----------------
__global__ void head2_kernel(const float* __restrict__ h, const float* __restrict__ Wh2,
                             const float* __restrict__ bh2, float* __restrict__ out) {
    int gtid = blockIdx.x * blockDim.x + threadIdx.x;
    int w = gtid >> 5;
    int lane = gtid & 31;
    if (w >= N_NODES) return;
    float2 v = *reinterpret_cast<const float2*>(h + (size_t)w * C + lane * 2);
    float s0 = v.x * Wh2[lane * 2] + v.y * Wh2[lane * 2 + 1];
    float s1 = v.x * Wh2[64 + lane * 2] + v.y * Wh2[64 + lane * 2 + 1];
#pragma unroll
    for (int o = 16; o > 0; o >>= 1) {
        s0 += __shfl_down_sync(0xffffffffu, s0, o);
        s1 += __shfl_down_sync(0xffffffffu, s1, o);
    }
    if (lane == 0) {
        out[(size_t)w * 2 + 0] = s0 + bh2[0];
        out[(size_t)w * 2 + 1] = s1 + bh2[1];
    }
}

// ---------------- launch ----------------
extern "C" void kernel_launch(void* const* d_in, const int* in_sizes, int n_in,
                              void* d_out, int out_size) {
    const float* x = (const float*)d_in[0];
    const int* ei32 = (const int*)d_in[1];
    const float* Wn[3] = {(const float*)d_in[2], (const float*)d_in[7], (const float*)d_in[12]};
    const float* bn[3] = {(const float*)d_in[3], (const float*)d_in[8], (const float*)d_in[13]};
    const float* Wr[3] = {(const float*)d_in[4], (const float*)d_in[9], (const float*)d_in[14]};
    const float* ga[3] = {(const float*)d_in[5], (const float*)d_in[10], (const float*)d_in[15]};
    const float* be[3] = {(const float*)d_in[6], (const float*)d_in[11], (const float*)d_in[16]};
    const float* Wh1 = (const float*)d_in[17];
    const float* bh1 = (const float*)d_in[18];
    const float* Wh2 = (const float*)d_in[19];
    const float* bh2 = (const float*)d_in[20];
    float* out = (float*)d_out;

    float *p_h1, *p_h2, *p_Wc, *p_Wh1p, *p_bh1p;
    cudaGetSymbolAddress((void**)&p_h1, g_h1);
    cudaGetSymbolAddress((void**)&p_h2, g_h2);
    cudaGetSymbolAddress((void**)&p_Wc, g_Wc);
    cudaGetSymbolAddress((void**)&p_Wh1p, g_Wh1p);
    cudaGetSymbolAddress((void**)&p_bh1p, g_bh1p);

    detect_kernel<<<1, 256>>>(ei32);
    decode_kernel<<<(N_EDGES + 255) / 256, 256>>>(ei32);
    pack_all_kernel<<<(3 * 2 * C * C + 255) / 256, 256>>>(
        Wn[0], Wr[0], Wn[1], Wr[1], Wn[2], Wr[2]);
    pack_head_kernel<<<(C * C + 255) / 256, 256>>>(Wh1, bh1);

    const int gemm_blocks = (N_NODES + 127) / 128;
    const int scat_blocks = (N_EDGES * 32 + 255) / 256;
    float* bufs[2] = {p_h1, p_h2};
    const float* h_in = x;

    for (int l = 0; l < 3; l++) {
        float* h_out = bufs[l & 1];
        if (l == 0) {
            zero_kernel<true><<<2048, 256>>>();
            scatter_kernel<false, true><<<scat_blocks, 256>>>(h_in);
            gemm_kernel<2 * C, true, false, false, true><<<gemm_blocks, 256>>>(
                h_in, p_Wc, bn[l], h_out);
        } else {
            zero_kernel<false><<<2048, 256>>>();
            scatter_kernel<true, false><<<scat_blocks, 256>>>(h_in);
            gemm_kernel<2 * C, true, true, false, true><<<gemm_blocks, 256>>>(
                h_in, p_Wc + (size_t)l * 2 * C * C, bn[l], h_out);
        }
        bnparam_kernel<<<1, 128>>>(ga[l], be[l]);
        h_in = h_out;
    }

    // head: layer-2 raw output is in bufs[0]=g_h1; apply its BN+ReLU on load.
    gemm_kernel<C, false, true, true, false><<<gemm_blocks, 256>>>(
        p_h1, p_Wh1p, p_bh1p, p_h2);
    head2_kernel<<<(N_NODES * 32 + 255) / 256, 256>>>(p_h2, Wh2, bh2, out);
}

// round 6
// speedup vs baseline: 1.3610x; 1.2104x over previous
#include <cuda_runtime.h>
#include <cuda_bf16.h>
#include <cstdint>

#define N_NODES 100000
#define N_EDGES 800000
#define C 128
#define EPS_BN 1e-5f

// ---------------- device scratch (no allocs allowed) ----------------
__device__ float g_agg[N_NODES * C];
__device__ float g_deg[N_NODES];
__device__ float g_h1[N_NODES * C];
__device__ float g_h2[N_NODES * C];
__device__ unsigned short g_Bw[3][2][128 * 256];   // [layer][hi/lo][n][k] bf16
__device__ unsigned short g_Bh[2][128 * 128];      // head [hi/lo][n][k]
__device__ float g_bh1p[C];
__device__ float g_sum[C];
__device__ float g_sumsq[C];
__device__ float g_scale[C];
__device__ float g_shift[C];
__device__ int g_src[N_EDGES];
__device__ int g_dst[N_EDGES];
__device__ int g_is64;

// ---------------- helpers ----------------
__device__ __forceinline__ uint32_t smem_u32(const void* p) {
    uint32_t a;
    asm("{ .reg .u64 t; cvta.to.shared.u64 t, %1; cvt.u32.u64 %0, t; }" : "=r"(a) : "l"(p));
    return a;
}
__device__ __forceinline__ void ldm4(uint32_t* r, uint32_t addr) {
    asm volatile("ldmatrix.sync.aligned.m8n8.x4.shared.b16 {%0,%1,%2,%3}, [%4];"
                 : "=r"(r[0]), "=r"(r[1]), "=r"(r[2]), "=r"(r[3]) : "r"(addr));
}
__device__ __forceinline__ void mma16816(float* c, const uint32_t* a, uint32_t b0, uint32_t b1) {
    asm volatile(
        "mma.sync.aligned.m16n8k16.row.col.f32.bf16.bf16.f32 "
        "{%0,%1,%2,%3}, {%4,%5,%6,%7}, {%8,%9}, {%0,%1,%2,%3};"
        : "+f"(c[0]), "+f"(c[1]), "+f"(c[2]), "+f"(c[3])
        : "r"(a[0]), "r"(a[1]), "r"(a[2]), "r"(a[3]), "r"(b0), "r"(b1));
}
__device__ __forceinline__ unsigned short bfbits(__nv_bfloat16 h) {
    return *reinterpret_cast<unsigned short*>(&h);
}

// ---------------- edge dtype detection + decode ----------------
__global__ void detect_kernel(const int* __restrict__ w) {
    __shared__ int acc[256];
    int tid = threadIdx.x;
    int v = 0;
    for (int i = tid; i < 1024; i += 256) v |= w[2 * i + 1];
    acc[tid] = v;
    __syncthreads();
    for (int s = 128; s > 0; s >>= 1) {
        if (tid < s) acc[tid] |= acc[tid + s];
        __syncthreads();
    }
    if (tid == 0) g_is64 = (acc[0] == 0) ? 1 : 0;
}

__global__ void decode_kernel(const int* __restrict__ w) {
    int e = blockIdx.x * blockDim.x + threadIdx.x;
    if (e >= N_EDGES) return;
    if (g_is64) {
        g_src[e] = w[2 * e];
        g_dst[e] = w[2 * (N_EDGES + e)];
    } else {
        g_src[e] = w[e];
        g_dst[e] = w[N_EDGES + e];
    }
}

// ---------------- pack weights into bf16 hi/lo [n][k] panels ----------------
__global__ void pack_all_kernel(const float* __restrict__ Wn0, const float* __restrict__ Wr0,
                                const float* __restrict__ Wn1, const float* __restrict__ Wr1,
                                const float* __restrict__ Wn2, const float* __restrict__ Wr2) {
    int idx = blockIdx.x * blockDim.x + threadIdx.x;
    if (idx >= 3 * 128 * 256) return;
    int layer = idx / (128 * 256);
    int r = idx % (128 * 256);
    int n = r / 256, k = r % 256;
    const float* Wn = (layer == 0) ? Wn0 : (layer == 1) ? Wn1 : Wn2;
    const float* Wr = (layer == 0) ? Wr0 : (layer == 1) ? Wr1 : Wr2;
    float w = (k < C) ? Wn[n * C + k] : Wr[n * C + (k - C)];
    __nv_bfloat16 hi = __float2bfloat16(w);
    __nv_bfloat16 lo = __float2bfloat16(w - __bfloat162float(hi));
    g_Bw[layer][0][r] = bfbits(hi);
    g_Bw[layer][1][r] = bfbits(lo);
}

__global__ void pack_head_kernel(const float* __restrict__ Wh1,
                                 const float* __restrict__ bh1) {
    int idx = blockIdx.x * blockDim.x + threadIdx.x;
    if (idx < 128 * 128) {
        int n = idx / 128, k = idx % 128;
        float w = (n < 64) ? Wh1[n * C + k] : 0.0f;
        __nv_bfloat16 hi = __float2bfloat16(w);
        __nv_bfloat16 lo = __float2bfloat16(w - __bfloat162float(hi));
        g_Bh[0][idx] = bfbits(hi);
        g_Bh[1][idx] = bfbits(lo);
    }
    if (idx < C) g_bh1p[idx] = (idx < 64) ? bh1[idx] : 0.0f;
}

// ---------------- zero agg (+deg) + stats ----------------
template <bool ZDEG>
__global__ void zero_kernel() {
    int stride = gridDim.x * blockDim.x;
    float4 z = make_float4(0.f, 0.f, 0.f, 0.f);
    for (int i = blockIdx.x * blockDim.x + threadIdx.x; i < N_NODES * C / 4; i += stride) {
        reinterpret_cast<float4*>(g_agg)[i] = z;
        if (ZDEG && i < N_NODES / 4) reinterpret_cast<float4*>(g_deg)[i] = z;
        if (i < C) { g_sum[i] = 0.f; g_sumsq[i] = 0.f; }
    }
}

// ---------------- edge scatter ----------------
template <bool XFORM, bool DEG>
__global__ void scatter_kernel(const float* __restrict__ h) {
    int gtid = blockIdx.x * blockDim.x + threadIdx.x;
    int e = gtid >> 5;
    int lane = gtid & 31;
    if (e >= N_EDGES) return;
    int s = g_src[e];
    int d = g_dst[e];
    float4 v = *reinterpret_cast<const float4*>(h + (size_t)s * C + lane * 4);
    if (XFORM) {
        float4 sc = reinterpret_cast<const float4*>(g_scale)[lane];
        float4 sh = reinterpret_cast<const float4*>(g_shift)[lane];
        v.x = fmaxf(v.x * sc.x + sh.x, 0.f);
        v.y = fmaxf(v.y * sc.y + sh.y, 0.f);
        v.z = fmaxf(v.z * sc.z + sh.z, 0.f);
        v.w = fmaxf(v.w * sc.w + sh.w, 0.f);
    }
    float* dstp = g_agg + (size_t)d * C + lane * 4;
    asm volatile("red.global.add.v4.f32 [%0], {%1,%2,%3,%4};"
                 :: "l"(dstp), "f"(v.x), "f"(v.y), "f"(v.z), "f"(v.w)
                 : "memory");
    if (DEG && lane == 0) atomicAdd(&g_deg[d], 1.0f);
}

// ---------------- mma.sync fused GEMM ----------------
// out[128x128 tile] = [mean | f(h)] @ W^T + bias ; bf16 split-3, fp32 accum.
// smem: A chunk hi/lo (128 x 72 halves each), B full-K hi/lo (128 x (KS+8) halves each).
template <int KS, bool SAGE, bool XFORM, bool RELU_OUT, bool STATS>
__global__ void __launch_bounds__(256, 1)
gemm_mma_kernel(const float* __restrict__ A, const unsigned short* __restrict__ Bpk,
                const float* __restrict__ bias, float* __restrict__ out) {
    constexpr int KSPAD = KS + 8;
    constexpr int AS_HI = 0;
    constexpr int AS_LO = 128 * 72 * 2;            // 18432
    constexpr int BS_HI = 2 * 128 * 72 * 2;        // 36864
    constexpr int BSZ = 128 * KSPAD * 2;
    constexpr int BS_LO = BS_HI + BSZ;
    constexpr int SMBIAS = BS_LO + BSZ;
    constexpr int STAGE_LD = 132;

    extern __shared__ char sm[];
    uint32_t smb = smem_u32(sm);
    int tid = threadIdx.x;
    int wid = tid >> 5;
    int lane = tid & 31;
    int row0 = blockIdx.x * 128;

    // B copy with pad (hi and lo)
    {
        const uint4* shi = reinterpret_cast<const uint4*>(Bpk);
        const uint4* slo = reinterpret_cast<const uint4*>(Bpk + 128 * KS);
        constexpr int CW = KS / 8;              // uint4 per row
        for (int i = tid; i < 128 * CW; i += 256) {
            int r = i / CW, cc = i % CW;
            *reinterpret_cast<uint4*>(sm + BS_HI + r * KSPAD * 2 + cc * 16) = shi[i];
            *reinterpret_cast<uint4*>(sm + BS_LO + r * KSPAD * 2 + cc * 16) = slo[i];
        }
    }
    if (tid < 32)
        reinterpret_cast<float4*>(sm + SMBIAS)[tid] =
            reinterpret_cast<const float4*>(bias)[tid];

    // A conversion ownership: row = tid>>1, half = tid&1 (32 cols of 64-chunk)
    int arow = tid >> 1;
    int ahalf = tid & 1;
    int grow = row0 + arow;
    bool valid = grow < N_NODES;
    float rd = 0.f;
    if (SAGE && valid) rd = 1.0f / fmaxf(g_deg[grow], 1.0f);

    // warp tiling: 4 (m) x 2 (n); warp tile 32 x 64
    int m0 = (wid >> 1) * 32;
    int n0 = (wid & 1) * 64;

    // ldmatrix base addresses
    uint32_t a_base[2], b_base_h[4], b_base_l[4];
#pragma unroll
    for (int mi = 0; mi < 2; mi++)
        a_base[mi] = smb + AS_HI + (uint32_t)(m0 + mi * 16 + (lane & 15)) * 144u +
                     ((lane >> 4) * 8u) * 2u;
#pragma unroll
    for (int g = 0; g < 4; g++) {
        uint32_t nidx = (uint32_t)(n0 + g * 16 + ((lane >> 4) << 3) + (lane & 7));
        uint32_t koff = (((lane >> 3) & 1) * 8u) * 2u;
        b_base_h[g] = smb + BS_HI + nidx * (KSPAD * 2u) + koff;
        b_base_l[g] = b_base_h[g] + (uint32_t)BSZ;
    }

    float acc[2][8][4];
#pragma unroll
    for (int mi = 0; mi < 2; mi++)
#pragma unroll
        for (int ni = 0; ni < 8; ni++)
#pragma unroll
            for (int r = 0; r < 4; r++) acc[mi][ni][r] = 0.f;

    constexpr int NCHUNK = KS / 64;
    for (int chunk = 0; chunk < NCHUNK; chunk++) {
        if (chunk > 0) __syncthreads();   // protect As reuse
        // convert 32 fp32 -> bf16 hi/lo into As
#pragma unroll
        for (int j8 = 0; j8 < 4; j8++) {
            int cc = ahalf * 32 + j8 * 8;         // col within chunk
            int gk = chunk * 64 + cc;             // global k
            float v[8];
            if (valid) {
                const float* srcp;
                bool agg_path = SAGE && (gk < C);
                if (agg_path) srcp = g_agg + (size_t)grow * C + gk;
                else srcp = A + (size_t)grow * C + (SAGE ? gk - C : gk);
                *reinterpret_cast<float4*>(&v[0]) = *reinterpret_cast<const float4*>(srcp);
                *reinterpret_cast<float4*>(&v[4]) = *reinterpret_cast<const float4*>(srcp + 4);
                if (agg_path) {
#pragma unroll
                    for (int j = 0; j < 8; j++) v[j] *= rd;
                } else if (XFORM) {
                    int cb = SAGE ? gk - C : gk;
#pragma unroll
                    for (int j = 0; j < 8; j++)
                        v[j] = fmaxf(v[j] * g_scale[cb + j] + g_shift[cb + j], 0.f);
                }
            } else {
#pragma unroll
                for (int j = 0; j < 8; j++) v[j] = 0.f;
            }
            uint32_t hw[4], lw[4];
#pragma unroll
            for (int j = 0; j < 4; j++) {
                __nv_bfloat16 h0 = __float2bfloat16(v[2 * j]);
                __nv_bfloat16 h1 = __float2bfloat16(v[2 * j + 1]);
                __nv_bfloat16 l0 = __float2bfloat16(v[2 * j] - __bfloat162float(h0));
                __nv_bfloat16 l1 = __float2bfloat16(v[2 * j + 1] - __bfloat162float(h1));
                hw[j] = (uint32_t)bfbits(h0) | ((uint32_t)bfbits(h1) << 16);
                lw[j] = (uint32_t)bfbits(l0) | ((uint32_t)bfbits(l1) << 16);
            }
            *reinterpret_cast<uint4*>(sm + AS_HI + arow * 144 + cc * 2) =
                make_uint4(hw[0], hw[1], hw[2], hw[3]);
            *reinterpret_cast<uint4*>(sm + AS_LO + arow * 144 + cc * 2) =
                make_uint4(lw[0], lw[1], lw[2], lw[3]);
        }
        __syncthreads();

#pragma unroll
        for (int ks = 0; ks < 4; ks++) {
            int kl = ks * 16;                 // k within chunk (A smem)
            int gk = chunk * 64 + kl;         // global k (B smem)
            uint32_t ah[2][4], al[2][4], bh[4][4], bl[4][4];
#pragma unroll
            for (int mi = 0; mi < 2; mi++) {
                ldm4(ah[mi], a_base[mi] + kl * 2);
                ldm4(al[mi], a_base[mi] + AS_LO + kl * 2);
            }
#pragma unroll
            for (int g = 0; g < 4; g++) {
                ldm4(bh[g], b_base_h[g] + gk * 2);
                ldm4(bl[g], b_base_l[g] + gk * 2);
            }
#pragma unroll
            for (int mi = 0; mi < 2; mi++)
#pragma unroll
                for (int g = 0; g < 4; g++) {
                    mma16816(acc[mi][2 * g + 0], ah[mi], bh[g][0], bh[g][1]);
                    mma16816(acc[mi][2 * g + 1], ah[mi], bh[g][2], bh[g][3]);
                    mma16816(acc[mi][2 * g + 0], ah[mi], bl[g][0], bl[g][1]);
                    mma16816(acc[mi][2 * g + 1], ah[mi], bl[g][2], bl[g][3]);
                    mma16816(acc[mi][2 * g + 0], al[mi], bh[g][0], bh[g][1]);
                    mma16816(acc[mi][2 * g + 1], al[mi], bh[g][2], bh[g][3]);
                }
        }
    }
    __syncthreads();   // all warps done with B before stage overlay

    // epilogue: bias (+relu), stage to smem (overlaying B region)
    float* stage = reinterpret_cast<float*>(sm + BS_HI);
    const float* sbias = reinterpret_cast<const float*>(sm + SMBIAS);
    int qr = lane >> 2, qc = lane & 3;
#pragma unroll
    for (int mi = 0; mi < 2; mi++) {
        int mA = m0 + mi * 16 + qr;
        int mB = mA + 8;
        bool vA = (row0 + mA) < N_NODES;
        bool vB = (row0 + mB) < N_NODES;
#pragma unroll
        for (int ni = 0; ni < 8; ni++) {
            int n = n0 + ni * 8 + qc * 2;
            float2 pA, pB;
            pA.x = acc[mi][ni][0] + sbias[n];
            pA.y = acc[mi][ni][1] + sbias[n + 1];
            pB.x = acc[mi][ni][2] + sbias[n];
            pB.y = acc[mi][ni][3] + sbias[n + 1];
            if (RELU_OUT) {
                pA.x = fmaxf(pA.x, 0.f); pA.y = fmaxf(pA.y, 0.f);
                pB.x = fmaxf(pB.x, 0.f); pB.y = fmaxf(pB.y, 0.f);
            }
            if (!vA) pA = make_float2(0.f, 0.f);
            if (!vB) pB = make_float2(0.f, 0.f);
            *reinterpret_cast<float2*>(stage + mA * STAGE_LD + n) = pA;
            *reinterpret_cast<float2*>(stage + mB * STAGE_LD + n) = pB;
        }
    }
    __syncthreads();

    if (STATS && tid < C) {
        float s = 0.f, q = 0.f;
        for (int r = 0; r < 128; r++) {
            float v = stage[r * STAGE_LD + tid];
            s += v;
            q += v * v;
        }
        atomicAdd(&g_sum[tid], s);
        atomicAdd(&g_sumsq[tid], q);
    }

    for (int idx = tid; idx < 128 * 32; idx += 256) {
        int r = idx >> 5, c4 = idx & 31;
        int row = row0 + r;
        if (row >= N_NODES) continue;
        *reinterpret_cast<float4*>(out + (size_t)row * C + c4 * 4) =
            *reinterpret_cast<const float4*>(stage + r * STAGE_LD + c4 * 4);
    }
}

__global__ void bnparam_kernel(const float* __restrict__ g, const float* __restrict__ be) {
    int c = threadIdx.x;
    if (c >= C) return;
    float m = g_sum[c] / (float)N_NODES;
    float v = g_sumsq[c] / (float)N_NODES - m * m;
    float sc = g[c] * rsqrtf(fmaxf(v, 0.f) + EPS_BN);
    g_scale[c] = sc;
    g_shift[c] = be[c] - m * sc;
}

// ---------------- head-2 ----------------
__global__ void head2_kernel(const float* __restrict__ h, const float* __restrict__ Wh2,
                             const float* __restrict__ bh2, float* __restrict__ out) {
    int gtid = blockIdx.x * blockDim.x + threadIdx.x;
    int w = gtid >> 5;
    int lane = gtid & 31;
    if (w >= N_NODES) return;
    float2 v = *reinterpret_cast<const float2*>(h + (size_t)w * C + lane * 2);
    float s0 = v.x * Wh2[lane * 2] + v.y * Wh2[lane * 2 + 1];
    float s1 = v.x * Wh2[64 + lane * 2] + v.y * Wh2[64 + lane * 2 + 1];
#pragma unroll
    for (int o = 16; o > 0; o >>= 1) {
        s0 += __shfl_down_sync(0xffffffffu, s0, o);
        s1 += __shfl_down_sync(0xffffffffu, s1, o);
    }
    if (lane == 0) {
        out[(size_t)w * 2 + 0] = s0 + bh2[0];
        out[(size_t)w * 2 + 1] = s1 + bh2[1];
    }
}

// ---------------- launch ----------------
extern "C" void kernel_launch(void* const* d_in, const int* in_sizes, int n_in,
                              void* d_out, int out_size) {
    const float* x = (const float*)d_in[0];
    const int* ei32 = (const int*)d_in[1];
    const float* Wn[3] = {(const float*)d_in[2], (const float*)d_in[7], (const float*)d_in[12]};
    const float* bn[3] = {(const float*)d_in[3], (const float*)d_in[8], (const float*)d_in[13]};
    const float* Wr[3] = {(const float*)d_in[4], (const float*)d_in[9], (const float*)d_in[14]};
    const float* ga[3] = {(const float*)d_in[5], (const float*)d_in[10], (const float*)d_in[15]};
    const float* be[3] = {(const float*)d_in[6], (const float*)d_in[11], (const float*)d_in[16]};
    const float* Wh1 = (const float*)d_in[17];
    const float* bh1 = (const float*)d_in[18];
    const float* Wh2 = (const float*)d_in[19];
    const float* bh2 = (const float*)d_in[20];
    float* out = (float*)d_out;

    float *p_h1, *p_h2, *p_bh1p;
    unsigned short *p_Bw, *p_Bh;
    cudaGetSymbolAddress((void**)&p_h1, g_h1);
    cudaGetSymbolAddress((void**)&p_h2, g_h2);
    cudaGetSymbolAddress((void**)&p_Bw, g_Bw);
    cudaGetSymbolAddress((void**)&p_Bh, g_Bh);
    cudaGetSymbolAddress((void**)&p_bh1p, g_bh1p);

    // smem sizes: layers 36864 + 2*128*264*2 + 512 = 172544 ; head 36864 + 2*128*136*2 + 512 = 107008
    const int SMEM_L = 36864 + 2 * 128 * 264 * 2 + 512;
    const int SMEM_H = 36864 + 2 * 128 * 136 * 2 + 512;
    cudaFuncSetAttribute(gemm_mma_kernel<256, true, false, false, true>,
                         cudaFuncAttributeMaxDynamicSharedMemorySize, SMEM_L);
    cudaFuncSetAttribute(gemm_mma_kernel<256, true, true, false, true>,
                         cudaFuncAttributeMaxDynamicSharedMemorySize, SMEM_L);
    cudaFuncSetAttribute(gemm_mma_kernel<128, false, true, true, false>,
                         cudaFuncAttributeMaxDynamicSharedMemorySize, SMEM_H);

    detect_kernel<<<1, 256>>>(ei32);
    decode_kernel<<<(N_EDGES + 255) / 256, 256>>>(ei32);
    pack_all_kernel<<<(3 * 128 * 256 + 255) / 256, 256>>>(
        Wn[0], Wr[0], Wn[1], Wr[1], Wn[2], Wr[2]);
    pack_head_kernel<<<(128 * 128 + 255) / 256, 256>>>(Wh1, bh1);

    const int gemm_blocks = (N_NODES + 127) / 128;
    const int scat_blocks = (N_EDGES * 32 + 255) / 256;
    float* bufs[2] = {p_h1, p_h2};
    const float* h_in = x;

    for (int l = 0; l < 3; l++) {
        float* h_out = bufs[l & 1];
        if (l == 0) {
            zero_kernel<true><<<2048, 256>>>();
            scatter_kernel<false, true><<<scat_blocks, 256>>>(h_in);
            gemm_mma_kernel<256, true, false, false, true><<<gemm_blocks, 256, SMEM_L>>>(
                h_in, p_Bw, bn[l], h_out);
        } else {
            zero_kernel<false><<<2048, 256>>>();
            scatter_kernel<true, false><<<scat_blocks, 256>>>(h_in);
            gemm_mma_kernel<256, true, true, false, true><<<gemm_blocks, 256, SMEM_L>>>(
                h_in, p_Bw + (size_t)l * 2 * 128 * 256, bn[l], h_out);
        }
        bnparam_kernel<<<1, 128>>>(ga[l], be[l]);
        h_in = h_out;
    }

    // head: layer-2 raw output in bufs[0]=g_h1; BN+ReLU applied on A-load.
    gemm_mma_kernel<128, false, true, true, false><<<gemm_blocks, 256, SMEM_H>>>(
        p_h1, p_Bh, p_bh1p, p_h2);
    head2_kernel<<<(N_NODES * 32 + 255) / 256, 256>>>(p_h2, Wh2, bh2, out);
}

// round 7
// speedup vs baseline: 2.1937x; 1.6119x over previous
#include <cuda_runtime.h>
#include <cuda_bf16.h>
#include <cstdint>

#define N_NODES 100000
#define N_EDGES 800000
#define C 128
#define EPS_BN 1e-5f
#define NB ((N_NODES + 255) / 256)   // 391 scan blocks

// ---------------- device scratch (no allocs allowed) ----------------
__device__ float g_agg[N_NODES * C];
__device__ float g_h1[N_NODES * C];
__device__ float g_h2[N_NODES * C];
__device__ unsigned short g_Bw[3][2][128 * 256];   // [layer][hi/lo][n][k] bf16
__device__ unsigned short g_Bh[2][128 * 128];      // head [hi/lo][n][k]
__device__ float g_bh1p[C];
__device__ float g_sum[C];
__device__ float g_sumsq[C];
__device__ float g_scale[C];
__device__ float g_shift[C];
__device__ int g_src[N_EDGES];
__device__ int g_dst[N_EDGES];
__device__ int g_esrc[N_EDGES];
__device__ int g_cnt[N_NODES];
__device__ int g_rowptr[N_NODES + 1];
__device__ int g_cursor[N_NODES];
__device__ int g_bsum[NB];
__device__ int g_is64;

// ---------------- helpers ----------------
__device__ __forceinline__ uint32_t smem_u32(const void* p) {
    uint32_t a;
    asm("{ .reg .u64 t; cvta.to.shared.u64 t, %1; cvt.u32.u64 %0, t; }" : "=r"(a) : "l"(p));
    return a;
}
__device__ __forceinline__ void ldm4(uint32_t* r, uint32_t addr) {
    asm volatile("ldmatrix.sync.aligned.m8n8.x4.shared.b16 {%0,%1,%2,%3}, [%4];"
                 : "=r"(r[0]), "=r"(r[1]), "=r"(r[2]), "=r"(r[3]) : "r"(addr));
}
__device__ __forceinline__ void mma16816(float* c, const uint32_t* a, uint32_t b0, uint32_t b1) {
    asm volatile(
        "mma.sync.aligned.m16n8k16.row.col.f32.bf16.bf16.f32 "
        "{%0,%1,%2,%3}, {%4,%5,%6,%7}, {%8,%9}, {%0,%1,%2,%3};"
        : "+f"(c[0]), "+f"(c[1]), "+f"(c[2]), "+f"(c[3])
        : "r"(a[0]), "r"(a[1]), "r"(a[2]), "r"(a[3]), "r"(b0), "r"(b1));
}
__device__ __forceinline__ unsigned short bfbits(__nv_bfloat16 h) {
    return *reinterpret_cast<unsigned short*>(&h);
}

// ---------------- edge dtype detection ----------------
__global__ void detect_kernel(const int* __restrict__ w) {
    __shared__ int acc[256];
    int tid = threadIdx.x;
    int v = 0;
    for (int i = tid; i < 1024; i += 256) v |= w[2 * i + 1];
    acc[tid] = v;
    __syncthreads();
    for (int s = 128; s > 0; s >>= 1) {
        if (tid < s) acc[tid] |= acc[tid + s];
        __syncthreads();
    }
    if (tid == 0) g_is64 = (acc[0] == 0) ? 1 : 0;
}

// ---------------- CSR build ----------------
__global__ void zero_cnt_kernel() {
    int i = blockIdx.x * blockDim.x + threadIdx.x;
    if (i < N_NODES) g_cnt[i] = 0;
}

__global__ void decode_hist_kernel(const int* __restrict__ w) {
    int e = blockIdx.x * blockDim.x + threadIdx.x;
    if (e >= N_EDGES) return;
    int s, d;
    if (g_is64) {
        s = w[2 * e];
        d = w[2 * (N_EDGES + e)];
    } else {
        s = w[e];
        d = w[N_EDGES + e];
    }
    g_src[e] = s;
    g_dst[e] = d;
    atomicAdd(&g_cnt[d], 1);
}

__global__ void bsum_kernel() {
    __shared__ int sm[256];
    int i = blockIdx.x * 256 + threadIdx.x;
    sm[threadIdx.x] = (i < N_NODES) ? g_cnt[i] : 0;
    __syncthreads();
    for (int s = 128; s > 0; s >>= 1) {
        if (threadIdx.x < s) sm[threadIdx.x] += sm[threadIdx.x + s];
        __syncthreads();
    }
    if (threadIdx.x == 0) g_bsum[blockIdx.x] = sm[0];
}

__global__ void scan_bsum_kernel() {   // 1 block, 512 threads
    __shared__ int sm[512];
    int t = threadIdx.x;
    int val = (t < NB) ? g_bsum[t] : 0;
    sm[t] = val;
    __syncthreads();
    for (int off = 1; off < 512; off <<= 1) {
        int x = (t >= off) ? sm[t - off] : 0;
        __syncthreads();
        sm[t] += x;
        __syncthreads();
    }
    if (t < NB) g_bsum[t] = sm[t] - val;   // exclusive
}

__global__ void rowptr_kernel() {
    __shared__ int sm[256];
    int t = threadIdx.x;
    int i = blockIdx.x * 256 + t;
    int c = (i < N_NODES) ? g_cnt[i] : 0;
    sm[t] = c;
    __syncthreads();
    for (int off = 1; off < 256; off <<= 1) {
        int x = (t >= off) ? sm[t - off] : 0;
        __syncthreads();
        sm[t] += x;
        __syncthreads();
    }
    if (i < N_NODES) {
        int rp = g_bsum[blockIdx.x] + sm[t] - c;
        g_rowptr[i] = rp;
        g_cursor[i] = rp;
        if (i == N_NODES - 1) g_rowptr[N_NODES] = rp + c;
    }
}

__global__ void fill_kernel() {
    int e = blockIdx.x * blockDim.x + threadIdx.x;
    if (e >= N_EDGES) return;
    int pos = atomicAdd(&g_cursor[g_dst[e]], 1);
    g_esrc[pos] = g_src[e];
}

// ---------------- pack weights into bf16 hi/lo [n][k] panels ----------------
__global__ void pack_all_kernel(const float* __restrict__ Wn0, const float* __restrict__ Wr0,
                                const float* __restrict__ Wn1, const float* __restrict__ Wr1,
                                const float* __restrict__ Wn2, const float* __restrict__ Wr2) {
    int idx = blockIdx.x * blockDim.x + threadIdx.x;
    if (idx >= 3 * 128 * 256) return;
    int layer = idx / (128 * 256);
    int r = idx % (128 * 256);
    int n = r / 256, k = r % 256;
    const float* Wn = (layer == 0) ? Wn0 : (layer == 1) ? Wn1 : Wn2;
    const float* Wr = (layer == 0) ? Wr0 : (layer == 1) ? Wr1 : Wr2;
    float w = (k < C) ? Wn[n * C + k] : Wr[n * C + (k - C)];
    __nv_bfloat16 hi = __float2bfloat16(w);
    __nv_bfloat16 lo = __float2bfloat16(w - __bfloat162float(hi));
    g_Bw[layer][0][r] = bfbits(hi);
    g_Bw[layer][1][r] = bfbits(lo);
}

__global__ void pack_head_kernel(const float* __restrict__ Wh1,
                                 const float* __restrict__ bh1) {
    int idx = blockIdx.x * blockDim.x + threadIdx.x;
    if (idx < 128 * 128) {
        int n = idx / 128, k = idx % 128;
        float w = (n < 64) ? Wh1[n * C + k] : 0.0f;
        __nv_bfloat16 hi = __float2bfloat16(w);
        __nv_bfloat16 lo = __float2bfloat16(w - __bfloat162float(hi));
        g_Bh[0][idx] = bfbits(hi);
        g_Bh[1][idx] = bfbits(lo);
    }
    if (idx < C) g_bh1p[idx] = (idx < 64) ? bh1[idx] : 0.0f;
}

// ---------------- CSR aggregation: warp per dst node, mean applied at store ----------------
template <bool XFORM>
__global__ void agg_kernel(const float* __restrict__ h) {
    int gt = blockIdx.x * blockDim.x + threadIdx.x;
    int w = gt >> 5;
    int lane = gt & 31;
    if (w >= N_NODES) return;
    int beg = g_rowptr[w], end = g_rowptr[w + 1];
    float4 acc = make_float4(0.f, 0.f, 0.f, 0.f);
    float4 sc, sh;
    if (XFORM) {
        sc = reinterpret_cast<const float4*>(g_scale)[lane];
        sh = reinterpret_cast<const float4*>(g_shift)[lane];
    }
    int e = beg;
    for (; e + 1 < end; e += 2) {
        int s0 = __ldg(&g_esrc[e]);
        int s1 = __ldg(&g_esrc[e + 1]);
        float4 v0 = *reinterpret_cast<const float4*>(h + (size_t)s0 * C + lane * 4);
        float4 v1 = *reinterpret_cast<const float4*>(h + (size_t)s1 * C + lane * 4);
        if (XFORM) {
            v0.x = fmaxf(fmaf(v0.x, sc.x, sh.x), 0.f);
            v0.y = fmaxf(fmaf(v0.y, sc.y, sh.y), 0.f);
            v0.z = fmaxf(fmaf(v0.z, sc.z, sh.z), 0.f);
            v0.w = fmaxf(fmaf(v0.w, sc.w, sh.w), 0.f);
            v1.x = fmaxf(fmaf(v1.x, sc.x, sh.x), 0.f);
            v1.y = fmaxf(fmaf(v1.y, sc.y, sh.y), 0.f);
            v1.z = fmaxf(fmaf(v1.z, sc.z, sh.z), 0.f);
            v1.w = fmaxf(fmaf(v1.w, sc.w, sh.w), 0.f);
        }
        acc.x += v0.x + v1.x;
        acc.y += v0.y + v1.y;
        acc.z += v0.z + v1.z;
        acc.w += v0.w + v1.w;
    }
    if (e < end) {
        int s0 = __ldg(&g_esrc[e]);
        float4 v0 = *reinterpret_cast<const float4*>(h + (size_t)s0 * C + lane * 4);
        if (XFORM) {
            v0.x = fmaxf(fmaf(v0.x, sc.x, sh.x), 0.f);
            v0.y = fmaxf(fmaf(v0.y, sc.y, sh.y), 0.f);
            v0.z = fmaxf(fmaf(v0.z, sc.z, sh.z), 0.f);
            v0.w = fmaxf(fmaf(v0.w, sc.w, sh.w), 0.f);
        }
        acc.x += v0.x;
        acc.y += v0.y;
        acc.z += v0.z;
        acc.w += v0.w;
    }
    float rd = 1.f / fmaxf((float)(end - beg), 1.f);
    acc.x *= rd; acc.y *= rd; acc.z *= rd; acc.w *= rd;
    *reinterpret_cast<float4*>(g_agg + (size_t)w * C + lane * 4) = acc;
}

// ---------------- mma.sync fused GEMM (per-chunk B reload, 2 CTAs/SM) ----------------
// smem layout (fixed): A_hi 18432 | A_lo 18432 | B_hi 18432 | B_lo 18432 | bias 512
#define AS_HI 0
#define AS_LO 18432
#define BS_HI 36864
#define BS_LO 55296
#define SMBIAS 73728
#define SM_TOTAL 74240
#define STAGE_LD 132

template <int KS, bool SAGE, bool XFORM, bool RELU_OUT, bool STATS>
__global__ void __launch_bounds__(256, 2)
gemm_mma_kernel(const float* __restrict__ A, const unsigned short* __restrict__ Bpk,
                const float* __restrict__ bias, float* __restrict__ out) {
    extern __shared__ char sm[];
    uint32_t smb = smem_u32(sm);
    int tid = threadIdx.x;
    int wid = tid >> 5;
    int lane = tid & 31;
    int row0 = blockIdx.x * 128;

    if (tid < 32)
        reinterpret_cast<float4*>(sm + SMBIAS)[tid] =
            reinterpret_cast<const float4*>(bias)[tid];

    // A conversion ownership: row = tid>>1, half = tid&1 (32 cols of the 64-chunk)
    int arow = tid >> 1;
    int ahalf = tid & 1;
    int grow = row0 + arow;
    bool valid = grow < N_NODES;

    // warp tiling: 4 (m) x 2 (n); warp tile 32 x 64
    int m0 = (wid >> 1) * 32;
    int n0 = (wid & 1) * 64;

    uint32_t a_base[2], b_base[4];
#pragma unroll
    for (int mi = 0; mi < 2; mi++)
        a_base[mi] = smb + AS_HI + (uint32_t)(m0 + mi * 16 + (lane & 15)) * 144u +
                     ((lane >> 4) * 8u) * 2u;
#pragma unroll
    for (int g = 0; g < 4; g++) {
        uint32_t nidx = (uint32_t)(n0 + g * 16 + ((lane >> 4) << 3) + (lane & 7));
        uint32_t koff = (((lane >> 3) & 1) * 8u) * 2u;
        b_base[g] = smb + BS_HI + nidx * 144u + koff;
    }

    float acc[2][8][4];
#pragma unroll
    for (int mi = 0; mi < 2; mi++)
#pragma unroll
        for (int ni = 0; ni < 8; ni++)
#pragma unroll
            for (int r = 0; r < 4; r++) acc[mi][ni][r] = 0.f;

    constexpr int NCHUNK = KS / 64;
    for (int chunk = 0; chunk < NCHUNK; chunk++) {
        if (chunk > 0) __syncthreads();    // previous MMA done with smem
        // B chunk copy (hi+lo): 128 rows x 8 uint4 each
        for (int i = tid; i < 1024; i += 256) {
            int r = i >> 3, cc = i & 7;
            *reinterpret_cast<uint4*>(sm + BS_HI + r * 144 + cc * 16) =
                *reinterpret_cast<const uint4*>(Bpk + (size_t)r * KS + chunk * 64 + cc * 8);
            *reinterpret_cast<uint4*>(sm + BS_LO + r * 144 + cc * 16) =
                *reinterpret_cast<const uint4*>(Bpk + (size_t)128 * KS + (size_t)r * KS +
                                                chunk * 64 + cc * 8);
        }
        // A chunk convert: 32 values per thread
#pragma unroll
        for (int j8 = 0; j8 < 4; j8++) {
            int cc = ahalf * 32 + j8 * 8;        // col within chunk
            int gk = chunk * 64 + cc;            // global k
            float v[8];
            if (valid) {
                const float* srcp;
                bool agg_path = SAGE && (gk < C);
                if (agg_path) srcp = g_agg + (size_t)grow * C + gk;
                else srcp = A + (size_t)grow * C + (SAGE ? gk - C : gk);
                *reinterpret_cast<float4*>(&v[0]) = *reinterpret_cast<const float4*>(srcp);
                *reinterpret_cast<float4*>(&v[4]) = *reinterpret_cast<const float4*>(srcp + 4);
                if (!agg_path && XFORM) {
                    int cb = SAGE ? gk - C : gk;
#pragma unroll
                    for (int j = 0; j < 8; j++)
                        v[j] = fmaxf(v[j] * g_scale[cb + j] + g_shift[cb + j], 0.f);
                }
            } else {
#pragma unroll
                for (int j = 0; j < 8; j++) v[j] = 0.f;
            }
            uint32_t hw[4], lw[4];
#pragma unroll
            for (int j = 0; j < 4; j++) {
                __nv_bfloat16 h0 = __float2bfloat16(v[2 * j]);
                __nv_bfloat16 h1 = __float2bfloat16(v[2 * j + 1]);
                __nv_bfloat16 l0 = __float2bfloat16(v[2 * j] - __bfloat162float(h0));
                __nv_bfloat16 l1 = __float2bfloat16(v[2 * j + 1] - __bfloat162float(h1));
                hw[j] = (uint32_t)bfbits(h0) | ((uint32_t)bfbits(h1) << 16);
                lw[j] = (uint32_t)bfbits(l0) | ((uint32_t)bfbits(l1) << 16);
            }
            *reinterpret_cast<uint4*>(sm + AS_HI + arow * 144 + cc * 2) =
                make_uint4(hw[0], hw[1], hw[2], hw[3]);
            *reinterpret_cast<uint4*>(sm + AS_LO + arow * 144 + cc * 2) =
                make_uint4(lw[0], lw[1], lw[2], lw[3]);
        }
        __syncthreads();

#pragma unroll
        for (int ks = 0; ks < 4; ks++) {
            int kl = ks * 16;
            uint32_t ah[2][4], al[2][4], bh[4][4], bl[4][4];
#pragma unroll
            for (int mi = 0; mi < 2; mi++) {
                ldm4(ah[mi], a_base[mi] + kl * 2);
                ldm4(al[mi], a_base[mi] + (AS_LO - AS_HI) + kl * 2);
            }
#pragma unroll
            for (int g = 0; g < 4; g++) {
                ldm4(bh[g], b_base[g] + kl * 2);
                ldm4(bl[g], b_base[g] + (BS_LO - BS_HI) + kl * 2);
            }
#pragma unroll
            for (int mi = 0; mi < 2; mi++)
#pragma unroll
                for (int g = 0; g < 4; g++) {
                    mma16816(acc[mi][2 * g + 0], ah[mi], bh[g][0], bh[g][1]);
                    mma16816(acc[mi][2 * g + 1], ah[mi], bh[g][2], bh[g][3]);
                    mma16816(acc[mi][2 * g + 0], ah[mi], bl[g][0], bl[g][1]);
                    mma16816(acc[mi][2 * g + 1], ah[mi], bl[g][2], bl[g][3]);
                    mma16816(acc[mi][2 * g + 0], al[mi], bh[g][0], bh[g][1]);
                    mma16816(acc[mi][2 * g + 1], al[mi], bh[g][2], bh[g][3]);
                }
        }
    }
    __syncthreads();   // all warps done before stage overlay

    // epilogue: bias (+relu), stage to smem (overlaying A/B regions)
    float* stage = reinterpret_cast<float*>(sm);
    const float* sbias = reinterpret_cast<const float*>(sm + SMBIAS);
    int qr = lane >> 2, qc = lane & 3;
#pragma unroll
    for (int mi = 0; mi < 2; mi++) {
        int mA = m0 + mi * 16 + qr;
        int mB = mA + 8;
        bool vA = (row0 + mA) < N_NODES;
        bool vB = (row0 + mB) < N_NODES;
#pragma unroll
        for (int ni = 0; ni < 8; ni++) {
            int n = n0 + ni * 8 + qc * 2;
            float2 pA, pB;
            pA.x = acc[mi][ni][0] + sbias[n];
            pA.y = acc[mi][ni][1] + sbias[n + 1];
            pB.x = acc[mi][ni][2] + sbias[n];
            pB.y = acc[mi][ni][3] + sbias[n + 1];
            if (RELU_OUT) {
                pA.x = fmaxf(pA.x, 0.f); pA.y = fmaxf(pA.y, 0.f);
                pB.x = fmaxf(pB.x, 0.f); pB.y = fmaxf(pB.y, 0.f);
            }
            if (!vA) pA = make_float2(0.f, 0.f);
            if (!vB) pB = make_float2(0.f, 0.f);
            *reinterpret_cast<float2*>(stage + mA * STAGE_LD + n) = pA;
            *reinterpret_cast<float2*>(stage + mB * STAGE_LD + n) = pB;
        }
    }
    __syncthreads();

    if (STATS && tid < C) {
        float s = 0.f, q = 0.f;
        for (int r = 0; r < 128; r++) {
            float v = stage[r * STAGE_LD + tid];
            s += v;
            q += v * v;
        }
        atomicAdd(&g_sum[tid], s);
        atomicAdd(&g_sumsq[tid], q);
    }

    for (int idx = tid; idx < 128 * 32; idx += 256) {
        int r = idx >> 5, c4 = idx & 31;
        int row = row0 + r;
        if (row >= N_NODES) continue;
        *reinterpret_cast<float4*>(out + (size_t)row * C + c4 * 4) =
            *reinterpret_cast<const float4*>(stage + r * STAGE_LD + c4 * 4);
    }
}

__global__ void bnparam_kernel(const float* __restrict__ g, const float* __restrict__ be) {
    int c = threadIdx.x;
    if (c >= C) return;
    float m = g_sum[c] / (float)N_NODES;
    float v = g_sumsq[c] / (float)N_NODES - m * m;
    float sc = g[c] * rsqrtf(fmaxf(v, 0.f) + EPS_BN);
    g_scale[c] = sc;
    g_shift[c] = be[c] - m * sc;
    g_sum[c] = 0.f;        // reset for next layer / next replay
    g_sumsq[c] = 0.f;
}

// ---------------- head-2 ----------------
__global__ void head2_kernel(const float* __restrict__ h, const float* __restrict__ Wh2,
                             const float* __restrict__ bh2, float* __restrict__ out) {
    int gtid = blockIdx.x * blockDim.x + threadIdx.x;
    int w = gtid >> 5;
    int lane = gtid & 31;
    if (w >= N_NODES) return;
    float2 v = *reinterpret_cast<const float2*>(h + (size_t)w * C + lane * 2);
    float s0 = v.x * Wh2[lane * 2] + v.y * Wh2[lane * 2 + 1];
    float s1 = v.x * Wh2[64 + lane * 2] + v.y * Wh2[64 + lane * 2 + 1];
#pragma unroll
    for (int o = 16; o > 0; o >>= 1) {
        s0 += __shfl_down_sync(0xffffffffu, s0, o);
        s1 += __shfl_down_sync(0xffffffffu, s1, o);
    }
    if (lane == 0) {
        out[(size_t)w * 2 + 0] = s0 + bh2[0];
        out[(size_t)w * 2 + 1] = s1 + bh2[1];
    }
}

// ---------------- launch ----------------
extern "C" void kernel_launch(void* const* d_in, const int* in_sizes, int n_in,
                              void* d_out, int out_size) {
    const float* x = (const float*)d_in[0];
    const int* ei32 = (const int*)d_in[1];
    const float* Wn[3] = {(const float*)d_in[2], (const float*)d_in[7], (const float*)d_in[12]};
    const float* bn[3] = {(const float*)d_in[3], (const float*)d_in[8], (const float*)d_in[13]};
    const float* Wr[3] = {(const float*)d_in[4], (const float*)d_in[9], (const float*)d_in[14]};
    const float* ga[3] = {(const float*)d_in[5], (const float*)d_in[10], (const float*)d_in[15]};
    const float* be[3] = {(const float*)d_in[6], (const float*)d_in[11], (const float*)d_in[16]};
    const float* Wh1 = (const float*)d_in[17];
    const float* bh1 = (const float*)d_in[18];
    const float* Wh2 = (const float*)d_in[19];
    const float* bh2 = (const float*)d_in[20];
    float* out = (float*)d_out;

    float *p_h1, *p_h2, *p_bh1p;
    unsigned short *p_Bw, *p_Bh;
    cudaGetSymbolAddress((void**)&p_h1, g_h1);
    cudaGetSymbolAddress((void**)&p_h2, g_h2);
    cudaGetSymbolAddress((void**)&p_Bw, g_Bw);
    cudaGetSymbolAddress((void**)&p_Bh, g_Bh);
    cudaGetSymbolAddress((void**)&p_bh1p, g_bh1p);

    cudaFuncSetAttribute(gemm_mma_kernel<256, true, false, false, true>,
                         cudaFuncAttributeMaxDynamicSharedMemorySize, SM_TOTAL);
    cudaFuncSetAttribute(gemm_mma_kernel<256, true, true, false, true>,
                         cudaFuncAttributeMaxDynamicSharedMemorySize, SM_TOTAL);
    cudaFuncSetAttribute(gemm_mma_kernel<128, false, true, true, false>,
                         cudaFuncAttributeMaxDynamicSharedMemorySize, SM_TOTAL);

    // CSR build (once per launch; graph constant across layers)
    detect_kernel<<<1, 256>>>(ei32);
    zero_cnt_kernel<<<NB, 256>>>();
    decode_hist_kernel<<<(N_EDGES + 255) / 256, 256>>>(ei32);
    bsum_kernel<<<NB, 256>>>();
    scan_bsum_kernel<<<1, 512>>>();
    rowptr_kernel<<<NB, 256>>>();
    fill_kernel<<<(N_EDGES + 255) / 256, 256>>>();
    pack_all_kernel<<<(3 * 128 * 256 + 255) / 256, 256>>>(
        Wn[0], Wr[0], Wn[1], Wr[1], Wn[2], Wr[2]);
    pack_head_kernel<<<(128 * 128 + 255) / 256, 256>>>(Wh1, bh1);

    const int gemm_blocks = (N_NODES + 127) / 128;
    const int agg_blocks = (N_NODES * 32 + 255) / 256;
    float* bufs[2] = {p_h1, p_h2};
    const float* h_in = x;

    for (int l = 0; l < 3; l++) {
        float* h_out = bufs[l & 1];
        if (l == 0) {
            agg_kernel<false><<<agg_blocks, 256>>>(h_in);
            gemm_mma_kernel<256, true, false, false, true><<<gemm_blocks, 256, SM_TOTAL>>>(
                h_in, p_Bw, bn[l], h_out);
        } else {
            agg_kernel<true><<<agg_blocks, 256>>>(h_in);
            gemm_mma_kernel<256, true, true, false, true><<<gemm_blocks, 256, SM_TOTAL>>>(
                h_in, p_Bw + (size_t)l * 2 * 128 * 256, bn[l], h_out);
        }
        bnparam_kernel<<<1, 128>>>(ga[l], be[l]);
        h_in = h_out;
    }

    // head: layer-2 raw output in bufs[0]=g_h1; BN+ReLU applied on A-load.
    gemm_mma_kernel<128, false, true, true, false><<<gemm_blocks, 256, SM_TOTAL>>>(
        p_h1, p_Bh, p_bh1p, p_h2);
    head2_kernel<<<(N_NODES * 32 + 255) / 256, 256>>>(p_h2, Wh2, bh2, out);
}